// round 14
// baseline (speedup 1.0000x reference)
#include <cuda_runtime.h>
#include <cuda_fp16.h>

#define B    64
#define NB   32    // batch per half
#define NIN  2048
#define DIN  8
#define NOUT 32
#define DOUT 16
#define OD   512   // NOUT*DOUT

// Scratch (device globals: allocation-free at run time)
__device__ __align__(256) __half g_preds[(size_t)B * NIN * OD];  // 2 x 64 MB halves
__device__ float  g_s[B * OD];                     // s accumulator (zero-init; tails re-zero)
__device__ float  g_v[B * OD];                     // current v
__device__ float  g_vsum[B * OD];                  // v1 + v2 (raw3 via linearity)
__device__ int    g_cnt[B];                        // per-b tickets (zero-init; tails reset)

// ---- helpers ---------------------------------------------------------------
__device__ __forceinline__ __half2 u32_as_half2(unsigned u) {
    union { unsigned u; __half2 h; } c; c.u = u; return c.h;
}

// ---------------------------------------------------------------------------
// preds[b,n,od] = sum_i W[n,od,i] * x[b,n,i] for b in [B0, B0+NB)   (R8 version)
template <int B0>
__global__ __launch_bounds__(128, 8)
void k_preds(const float* __restrict__ x, const float* __restrict__ W) {
    const int n = blockIdx.x;
    const int t = threadIdx.x;          // 0..127
    __shared__ float xs[NB * DIN];      // x[B0:B0+NB, n, :]
    if (t < 64) {
        int b = t >> 1, h = t & 1;
        float4 xv = *(const float4*)(x + ((B0 + b) * NIN + n) * DIN + h * 4);
        *(float4*)(xs + b * DIN + h * 4) = xv;
    }
    __syncthreads();

    const float* Wn = W + (size_t)n * (NOUT * DOUT * DIN) + t * 32;  // 4 od * 8 i
    float4 w[8];
#pragma unroll
    for (int j = 0; j < 8; j++) w[j] = ((const float4*)Wn)[j];

    __half* outp = g_preds + (size_t)(B0 * NIN + n) * OD + t * 4;
#pragma unroll 4
    for (int b = 0; b < NB; b++) {
        float4 x0 = *(float4*)(xs + b * 8);
        float4 x1 = *(float4*)(xs + b * 8 + 4);
        float r0 = w[0].x*x0.x + w[0].y*x0.y + w[0].z*x0.z + w[0].w*x0.w
                 + w[1].x*x1.x + w[1].y*x1.y + w[1].z*x1.z + w[1].w*x1.w;
        float r1 = w[2].x*x0.x + w[2].y*x0.y + w[2].z*x0.z + w[2].w*x0.w
                 + w[3].x*x1.x + w[3].y*x1.y + w[3].z*x1.z + w[3].w*x1.w;
        float r2 = w[4].x*x0.x + w[4].y*x0.y + w[4].z*x0.z + w[4].w*x0.w
                 + w[5].x*x1.x + w[5].y*x1.y + w[5].z*x1.z + w[5].w*x1.w;
        float r3 = w[6].x*x0.x + w[6].y*x0.y + w[6].z*x0.z + w[6].w*x0.w
                 + w[7].x*x1.x + w[7].y*x1.y + w[7].z*x1.z + w[7].w*x1.w;
        union { uint2 u; __half2 h[2]; } pk;
        pk.h[0] = __floats2half2_rn(r0, r1);
        pk.h[1] = __floats2half2_rn(r2, r3);
        *(uint2*)(outp + (size_t)b * NIN * OD) = pk.u;
    }
}

// ---------------------------------------------------------------------------
// Ticket-gated tail: LAST block for batch b squashes + updates state.
// mode 0: v1 = squash(s/32) -> g_v, g_vsum
// mode 1: v2 = squash(s)    -> g_vsum += v2
// mode 2: v3 = squash(s)    -> outv
// Always: zero g_s[b], reset g_cnt[b].  Requires blockDim.x == 256.
__device__ __forceinline__ void routing_tail(int b, int nblocks, int mode,
                                             float* __restrict__ outv) {
    __syncthreads();
    __threadfence();
    __shared__ int last;
    if (threadIdx.x == 0)
        last = (atomicAdd(&g_cnt[b], 1) == nblocks - 1);
    __syncthreads();
    if (!last) return;
    __threadfence();

    const int t = threadIdx.x;                 // owns od 2t, 2t+1
    float s0 = g_s[b * OD + 2 * t];
    float s1 = g_s[b * OD + 2 * t + 1];
    if (mode == 0) { s0 *= (1.f / NOUT); s1 *= (1.f / NOUT); }
    float sq = s0 * s0 + s1 * s1;              // 8 lanes = one o (16 d)
    sq += __shfl_xor_sync(0xFFFFFFFFu, sq, 1);
    sq += __shfl_xor_sync(0xFFFFFFFFu, sq, 2);
    sq += __shfl_xor_sync(0xFFFFFFFFu, sq, 4);
    float scale = sq / ((1.f + sq) * sqrtf(sq + 1e-7f));
    float v0 = scale * s0, v1 = scale * s1;

    if (mode == 0) {
        g_v[b * OD + 2 * t] = v0;     g_v[b * OD + 2 * t + 1] = v1;
        g_vsum[b * OD + 2 * t] = v0;  g_vsum[b * OD + 2 * t + 1] = v1;
    } else if (mode == 1) {
        g_vsum[b * OD + 2 * t] += v0; g_vsum[b * OD + 2 * t + 1] += v1;
    } else {
        outv[b * OD + 2 * t] = v0;    outv[b * OD + 2 * t + 1] = v1;
    }
    g_s[b * OD + 2 * t] = 0.f;
    g_s[b * OD + 2 * t + 1] = 0.f;
    if (t == 0) g_cnt[b] = 0;
}

// ---------------------------------------------------------------------------
// Iteration 1 (per half): s1[b,od] = sum_n preds[b,n,od]; tail squashes (/32).
template <int B0>
__global__ __launch_bounds__(256, 8)
void k_s1() {
    const int b = B0 + blockIdx.y, c = blockIdx.x;
    const int t = threadIdx.x;  // 0..255
    const unsigned* p = (const unsigned*)g_preds
                      + (size_t)(b * NIN + c * 128) * (OD / 2) + t;
    float acx = 0.f, acy = 0.f;
#pragma unroll 8
    for (int n = 0; n < 128; n++) {
        float2 f = __half22float2(u32_as_half2(__ldg(p + (size_t)n * (OD / 2))));
        acx += f.x; acy += f.y;
    }
    atomicAdd(&g_s[b * OD + 2 * t],     acx);
    atomicAdd(&g_s[b * OD + 2 * t + 1], acy);
    routing_tail(b, 16, 0, nullptr);
}

// ---------------------------------------------------------------------------
// Fused agreement + batched softmax + weighted-s + tail squash.
// R14: 4 rows/warp, ALL 8 row-loads front-batched (MLP=8/warp), rows held in
// REGISTERS through all phases (no Phase-C re-read).
// grid (64 n-chunks, NB b); 8 warps; lane = o.
// PASS 0 (iter 2): raw2 = preds.v1 (g_v), tail mode 1 (vsum += v2).
// PASS 1 (iter 3): raw3 = preds.(v1+v2) (g_vsum), rw -> out_rw, tail mode 2.
template <int PASS, int B0>
__global__ __launch_bounds__(256, 3)
void k_agree(float* __restrict__ out_rw, float* __restrict__ outv) {
    const int b = B0 + blockIdx.y;
    const int warp = threadIdx.x >> 5, lane = threadIdx.x & 31;
    const int n0 = blockIdx.x * 32 + warp * 4;

    const uint4* pbase = (const uint4*)(g_preds + (size_t)(b * NIN + n0) * OD) + lane * 2;
    const int row_u4 = OD / 8;   // 64 uint4 per n-row

    // ---- Front-batch ALL 8 loads (4 rows x 2 uint4): 8 in flight ----
    uint4 q[8];
#pragma unroll
    for (int k = 0; k < 4; k++) {
        q[2 * k]     = __ldg(pbase + k * row_u4);
        q[2 * k + 1] = __ldg(pbase + k * row_u4 + 1);
    }

    const float* vin = (PASS == 0 ? g_v : g_vsum) + b * OD + lane * 16;
    float vr[16];
#pragma unroll
    for (int j = 0; j < 4; j++) *(float4*)(vr + 4 * j) = ((const float4*)vin)[j];

    // ---- Phase A: logits + exp for 4 rows (data already in regs) ----
    float e[4];
#pragma unroll
    for (int k = 0; k < 4; k++) {
        union { uint4 u; __half2 h[4]; } a0, a1;
        a0.u = q[2 * k]; a1.u = q[2 * k + 1];
        float t0 = 0.f, t1 = 0.f;
#pragma unroll
        for (int j = 0; j < 4; j++) {
            float2 g0 = __half22float2(a0.h[j]);
            float2 g1 = __half22float2(a1.h[j]);
            t0 = fmaf(g0.x, vr[2 * j], t0);
            t0 = fmaf(g0.y, vr[2 * j + 1], t0);
            t1 = fmaf(g1.x, vr[8 + 2 * j], t1);
            t1 = fmaf(g1.y, vr[8 + 2 * j + 1], t1);
        }
        e[k] = __expf(t0 + t1);   // |logit| <= ~6, no max-shift needed
    }

    // ---- Phase B: 4 interleaved 32-lane sum reductions ----
    float es[4];
#pragma unroll
    for (int k = 0; k < 4; k++) es[k] = e[k];
#pragma unroll
    for (int s = 16; s; s >>= 1) {
#pragma unroll
        for (int k = 0; k < 4; k++)
            es[k] += __shfl_xor_sync(0xFFFFFFFFu, es[k], s);
    }
#pragma unroll
    for (int k = 0; k < 4; k++) e[k] = __fdividef(e[k], es[k]);   // rw

    // ---- Phase C: accumulate s from REGISTERS; emit rw ----
    float sp[16];
#pragma unroll
    for (int d = 0; d < 16; d++) sp[d] = 0.f;
#pragma unroll
    for (int k = 0; k < 4; k++) {
        union { uint4 u; __half2 h[4]; } a0, a1;
        a0.u = q[2 * k]; a1.u = q[2 * k + 1];
        const float rw = e[k];
#pragma unroll
        for (int j = 0; j < 4; j++) {
            float2 g0 = __half22float2(a0.h[j]);
            float2 g1 = __half22float2(a1.h[j]);
            sp[2 * j]      = fmaf(rw, g0.x, sp[2 * j]);
            sp[2 * j + 1]  = fmaf(rw, g0.y, sp[2 * j + 1]);
            sp[8 + 2 * j]     = fmaf(rw, g1.x, sp[8 + 2 * j]);
            sp[8 + 2 * j + 1] = fmaf(rw, g1.y, sp[8 + 2 * j + 1]);
        }
        if (PASS == 1)
            out_rw[(b * NIN + n0 + k) * NOUT + lane] = rw;
    }

    // block-level reduction of s partials, then one atomicAdd per od
    __shared__ float red[8][OD];
#pragma unroll
    for (int j = 0; j < 4; j++)
        *(float4*)(&red[warp][lane * 16 + 4 * j]) = *(float4*)(sp + 4 * j);
    __syncthreads();
    for (int j = threadIdx.x; j < OD; j += 256) {
        float a = 0.f;
#pragma unroll
        for (int w = 0; w < 8; w++) a += red[w][j];
        atomicAdd(&g_s[b * OD + j], a);
    }

    routing_tail(b, 64, PASS == 0 ? 1 : 2, outv);
}

// ---------------------------------------------------------------------------
extern "C" void kernel_launch(void* const* d_in, const int* in_sizes, int n_in,
                              void* d_out, int out_size) {
    (void)in_sizes; (void)n_in; (void)out_size;
    const float* x = (const float*)d_in[0];   // [64, 2048, 8]
    const float* W = (const float*)d_in[1];   // [2048, 32, 16, 8]
    float* out = (float*)d_out;               // v (32768 floats) then rw (4194304)
    float* out_rw = out + B * OD;

    // Half 0
    k_preds<0><<<NIN, 128>>>(x, W);
    k_s1<0><<<dim3(16, NB), 256>>>();
    k_agree<0, 0><<<dim3(64, NB), 256>>>(nullptr, nullptr);
    k_agree<1, 0><<<dim3(64, NB), 256>>>(out_rw, out);

    // Half 1
    k_preds<NB><<<NIN, 128>>>(x, W);
    k_s1<NB><<<dim3(16, NB), 256>>>();
    k_agree<0, NB><<<dim3(64, NB), 256>>>(nullptr, nullptr);
    k_agree<1, NB><<<dim3(64, NB), 256>>>(out_rw, out);
}

// round 15
// speedup vs baseline: 1.1528x; 1.1528x over previous
#include <cuda_runtime.h>
#include <cuda_fp16.h>

#define B    64
#define NB   32    // batch per half
#define NIN  2048
#define DIN  8
#define NOUT 32
#define DOUT 16
#define OD   512   // NOUT*DOUT

// Scratch (device globals: allocation-free at run time)
__device__ __align__(256) __half g_preds[(size_t)B * NIN * OD];  // 2 x 64 MB halves
__device__ float  g_s[B * OD];                     // s accumulator (zero-init; tails re-zero)
__device__ float  g_v[B * OD];                     // current v
__device__ float  g_vsum[B * OD];                  // v1 + v2 (raw3 via linearity)
__device__ int    g_cnt[B];                        // per-b tickets (zero-init; tails reset)

// ---- helpers ---------------------------------------------------------------
__device__ __forceinline__ __half2 u32_as_half2(unsigned u) {
    union { unsigned u; __half2 h; } c; c.u = u; return c.h;
}
// Convert a row held as 2 uint4 (16 halves) into 16 floats.
__device__ __forceinline__ void row_to_float(uint4 r0, uint4 r1, float* p) {
    union { uint4 u; __half2 h[4]; } a0, a1;
    a0.u = r0; a1.u = r1;
#pragma unroll
    for (int j = 0; j < 4; j++) {
        float2 f0 = __half22float2(a0.h[j]);
        float2 f1 = __half22float2(a1.h[j]);
        p[2 * j]         = f0.x;
        p[2 * j + 1]     = f0.y;
        p[8 + 2 * j]     = f1.x;
        p[8 + 2 * j + 1] = f1.y;
    }
}

// ---------------------------------------------------------------------------
// preds[b,n,od] = sum_i W[n,od,i] * x[b,n,i] for b in [B0, B0+NB)   (R8 version)
template <int B0>
__global__ __launch_bounds__(128, 8)
void k_preds(const float* __restrict__ x, const float* __restrict__ W) {
    const int n = blockIdx.x;
    const int t = threadIdx.x;          // 0..127
    __shared__ float xs[NB * DIN];      // x[B0:B0+NB, n, :]
    if (t < 64) {
        int b = t >> 1, h = t & 1;
        float4 xv = *(const float4*)(x + ((B0 + b) * NIN + n) * DIN + h * 4);
        *(float4*)(xs + b * DIN + h * 4) = xv;
    }
    __syncthreads();

    const float* Wn = W + (size_t)n * (NOUT * DOUT * DIN) + t * 32;  // 4 od * 8 i
    float4 w[8];
#pragma unroll
    for (int j = 0; j < 8; j++) w[j] = ((const float4*)Wn)[j];

    __half* outp = g_preds + (size_t)(B0 * NIN + n) * OD + t * 4;
#pragma unroll 4
    for (int b = 0; b < NB; b++) {
        float4 x0 = *(float4*)(xs + b * 8);
        float4 x1 = *(float4*)(xs + b * 8 + 4);
        float r0 = w[0].x*x0.x + w[0].y*x0.y + w[0].z*x0.z + w[0].w*x0.w
                 + w[1].x*x1.x + w[1].y*x1.y + w[1].z*x1.z + w[1].w*x1.w;
        float r1 = w[2].x*x0.x + w[2].y*x0.y + w[2].z*x0.z + w[2].w*x0.w
                 + w[3].x*x1.x + w[3].y*x1.y + w[3].z*x1.z + w[3].w*x1.w;
        float r2 = w[4].x*x0.x + w[4].y*x0.y + w[4].z*x0.z + w[4].w*x0.w
                 + w[5].x*x1.x + w[5].y*x1.y + w[5].z*x1.z + w[5].w*x1.w;
        float r3 = w[6].x*x0.x + w[6].y*x0.y + w[6].z*x0.z + w[6].w*x0.w
                 + w[7].x*x1.x + w[7].y*x1.y + w[7].z*x1.z + w[7].w*x1.w;
        union { uint2 u; __half2 h[2]; } pk;
        pk.h[0] = __floats2half2_rn(r0, r1);
        pk.h[1] = __floats2half2_rn(r2, r3);
        *(uint2*)(outp + (size_t)b * NIN * OD) = pk.u;
    }
}

// ---------------------------------------------------------------------------
// Ticket-gated tail: LAST block for batch b squashes + updates state.
// mode 0: v1 = squash(s/32) -> g_v, g_vsum
// mode 1: v2 = squash(s)    -> g_vsum += v2
// mode 2: v3 = squash(s)    -> outv
// Always: zero g_s[b], reset g_cnt[b].  Requires blockDim.x == 256.
__device__ __forceinline__ void routing_tail(int b, int nblocks, int mode,
                                             float* __restrict__ outv) {
    __syncthreads();
    __threadfence();
    __shared__ int last;
    if (threadIdx.x == 0)
        last = (atomicAdd(&g_cnt[b], 1) == nblocks - 1);
    __syncthreads();
    if (!last) return;
    __threadfence();

    const int t = threadIdx.x;                 // owns od 2t, 2t+1
    float s0 = g_s[b * OD + 2 * t];
    float s1 = g_s[b * OD + 2 * t + 1];
    if (mode == 0) { s0 *= (1.f / NOUT); s1 *= (1.f / NOUT); }
    float sq = s0 * s0 + s1 * s1;              // 8 lanes = one o (16 d)
    sq += __shfl_xor_sync(0xFFFFFFFFu, sq, 1);
    sq += __shfl_xor_sync(0xFFFFFFFFu, sq, 2);
    sq += __shfl_xor_sync(0xFFFFFFFFu, sq, 4);
    float scale = sq / ((1.f + sq) * sqrtf(sq + 1e-7f));
    float v0 = scale * s0, v1 = scale * s1;

    if (mode == 0) {
        g_v[b * OD + 2 * t] = v0;     g_v[b * OD + 2 * t + 1] = v1;
        g_vsum[b * OD + 2 * t] = v0;  g_vsum[b * OD + 2 * t + 1] = v1;
    } else if (mode == 1) {
        g_vsum[b * OD + 2 * t] += v0; g_vsum[b * OD + 2 * t + 1] += v1;
    } else {
        outv[b * OD + 2 * t] = v0;    outv[b * OD + 2 * t + 1] = v1;
    }
    g_s[b * OD + 2 * t] = 0.f;
    g_s[b * OD + 2 * t + 1] = 0.f;
    if (t == 0) g_cnt[b] = 0;
}

// ---------------------------------------------------------------------------
// Iteration 1 (per half): s1[b,od] = sum_n preds[b,n,od]; tail squashes (/32).
template <int B0>
__global__ __launch_bounds__(256, 8)
void k_s1() {
    const int b = B0 + blockIdx.y, c = blockIdx.x;
    const int t = threadIdx.x;  // 0..255
    const unsigned* p = (const unsigned*)g_preds
                      + (size_t)(b * NIN + c * 128) * (OD / 2) + t;
    float acx = 0.f, acy = 0.f;
#pragma unroll 8
    for (int n = 0; n < 128; n++) {
        float2 f = __half22float2(u32_as_half2(__ldg(p + (size_t)n * (OD / 2))));
        acx += f.x; acy += f.y;
    }
    atomicAdd(&g_s[b * OD + 2 * t],     acx);
    atomicAdd(&g_s[b * OD + 2 * t + 1], acy);
    routing_tail(b, 16, 0, nullptr);
}

// ---------------------------------------------------------------------------
// Fused agreement + softmax + weighted-s, SINGLE PASS over preds.
// Softmax is per-row over lanes (o) — no cross-row dependency — so each row
// is loaded ONCE, converted ONCE, and consumed from registers. Rows are
// processed in PAIRS so the two butterfly reductions interleave (shared
// shuffle latency). 8 rows/warp; grid (32 n-chunks, NB b); lane = o.
// PASS 0 (iter 2): raw2 = preds.v1 (g_v), tail mode 1 (vsum += v2).
// PASS 1 (iter 3): raw3 = preds.(v1+v2) (g_vsum), rw -> out_rw, tail mode 2.
template <int PASS, int B0>
__global__ __launch_bounds__(256, 3)
void k_agree(float* __restrict__ out_rw, float* __restrict__ outv) {
    const int b = B0 + blockIdx.y;
    const int warp = threadIdx.x >> 5, lane = threadIdx.x & 31;
    const int n0 = blockIdx.x * 64 + warp * 8;

    const float* vin = (PASS == 0 ? g_v : g_vsum) + b * OD + lane * 16;
    float vr[16];
#pragma unroll
    for (int j = 0; j < 4; j++) *(float4*)(vr + 4 * j) = ((const float4*)vin)[j];

    const uint4* pbase = (const uint4*)(g_preds + (size_t)(b * NIN + n0) * OD) + lane * 2;
    const int row_u4 = OD / 8;   // 64 uint4 per n-row

    float sp[16];
#pragma unroll
    for (int d = 0; d < 16; d++) sp[d] = 0.f;

#pragma unroll
    for (int pr = 0; pr < 4; pr++) {
        // Load both rows of the pair (4 independent LDG.128).
        uint4 qa0 = __ldg(pbase + (2 * pr) * row_u4);
        uint4 qa1 = __ldg(pbase + (2 * pr) * row_u4 + 1);
        uint4 qb0 = __ldg(pbase + (2 * pr + 1) * row_u4);
        uint4 qb1 = __ldg(pbase + (2 * pr + 1) * row_u4 + 1);

        float pA[16], pB[16];
        row_to_float(qa0, qa1, pA);
        row_to_float(qb0, qb1, pB);

        // Dots (2 chains per row), exp (|logit| <= ~2.5, no max-shift needed).
        float tA0 = 0.f, tA1 = 0.f, tB0 = 0.f, tB1 = 0.f;
#pragma unroll
        for (int j = 0; j < 8; j++) {
            tA0 = fmaf(pA[j], vr[j], tA0);
            tA1 = fmaf(pA[8 + j], vr[8 + j], tA1);
            tB0 = fmaf(pB[j], vr[j], tB0);
            tB1 = fmaf(pB[8 + j], vr[8 + j], tB1);
        }
        float eA = __expf(tA0 + tA1);
        float eB = __expf(tB0 + tB1);

        // Two interleaved 32-lane sum reductions (shared shuffle latency).
        float sA = eA, sB = eB;
#pragma unroll
        for (int s = 16; s; s >>= 1) {
            sA += __shfl_xor_sync(0xFFFFFFFFu, sA, s);
            sB += __shfl_xor_sync(0xFFFFFFFFu, sB, s);
        }
        float rwA = __fdividef(eA, sA);
        float rwB = __fdividef(eB, sB);

        // Weighted accumulation straight from registers.
#pragma unroll
        for (int d = 0; d < 16; d++) {
            sp[d] = fmaf(rwA, pA[d], sp[d]);
            sp[d] = fmaf(rwB, pB[d], sp[d]);
        }
        if (PASS == 1) {
            out_rw[(b * NIN + n0 + 2 * pr) * NOUT + lane]     = rwA;
            out_rw[(b * NIN + n0 + 2 * pr + 1) * NOUT + lane] = rwB;
        }
    }

    // block-level reduction of s partials, then one atomicAdd per od
    __shared__ float red[8][OD];
#pragma unroll
    for (int j = 0; j < 4; j++)
        *(float4*)(&red[warp][lane * 16 + 4 * j]) = *(float4*)(sp + 4 * j);
    __syncthreads();
    for (int j = threadIdx.x; j < OD; j += 256) {
        float a = 0.f;
#pragma unroll
        for (int w = 0; w < 8; w++) a += red[w][j];
        atomicAdd(&g_s[b * OD + j], a);
    }

    routing_tail(b, 32, PASS == 0 ? 1 : 2, outv);
}

// ---------------------------------------------------------------------------
extern "C" void kernel_launch(void* const* d_in, const int* in_sizes, int n_in,
                              void* d_out, int out_size) {
    (void)in_sizes; (void)n_in; (void)out_size;
    const float* x = (const float*)d_in[0];   // [64, 2048, 8]
    const float* W = (const float*)d_in[1];   // [2048, 32, 16, 8]
    float* out = (float*)d_out;               // v (32768 floats) then rw (4194304)
    float* out_rw = out + B * OD;

    // Half 0
    k_preds<0><<<NIN, 128>>>(x, W);
    k_s1<0><<<dim3(16, NB), 256>>>();
    k_agree<0, 0><<<dim3(32, NB), 256>>>(nullptr, nullptr);
    k_agree<1, 0><<<dim3(32, NB), 256>>>(out_rw, out);

    // Half 1
    k_preds<NB><<<NIN, 128>>>(x, W);
    k_s1<NB><<<dim3(16, NB), 256>>>();
    k_agree<0, NB><<<dim3(32, NB), 256>>>(nullptr, nullptr);
    k_agree<1, NB><<<dim3(32, NB), 256>>>(out_rw, out);
}